// round 5
// baseline (speedup 1.0000x reference)
#include <cuda_runtime.h>
#include <cuda_bf16.h>
#include <cstdint>

#define NN      65536
#define EE      1048576
#define IN_DIM  500
#define KPAD1   512
#define HID     256
#define OUTD    64
#define ALPHA   0.1f

// ---------------- static device scratch ----------------
__device__ float g_h1[(size_t)NN * HID];
__device__ float g_h2[(size_t)NN * HID];
__device__ float g_h0[(size_t)NN * OUTD];
__device__ float g_hA[(size_t)NN * OUTD];
__device__ float g_hB[(size_t)NN * OUTD];
__device__ __nv_bfloat16 g_B1h[(size_t)HID * KPAD1];
__device__ __nv_bfloat16 g_B1l[(size_t)HID * KPAD1];
__device__ __nv_bfloat16 g_B2h[(size_t)HID * HID];
__device__ __nv_bfloat16 g_B2l[(size_t)HID * HID];
__device__ __nv_bfloat16 g_B3h[(size_t)OUTD * HID];
__device__ __nv_bfloat16 g_B3l[(size_t)OUTD * HID];
__device__ int   g_rowoff[NN + 1];
__device__ int   g_cursor[NN];
__device__ int2  g_edge[EE];     // (col, weight-bits)

// ---------------- helpers ----------------
__device__ __forceinline__ uint32_t smem_to_u32(const void* p) {
    uint32_t a;
    asm("{ .reg .u64 t; cvta.to.shared.u64 t, %1; cvt.u32.u64 %0, t; }" : "=r"(a) : "l"(p));
    return a;
}

__device__ __forceinline__ void ldmatrix_x4(uint32_t* r, uint32_t addr) {
    asm volatile("ldmatrix.sync.aligned.m8n8.x4.shared.b16 {%0,%1,%2,%3}, [%4];"
                 : "=r"(r[0]), "=r"(r[1]), "=r"(r[2]), "=r"(r[3]) : "r"(addr));
}

__device__ __forceinline__ void mma_bf16(float* c, const uint32_t* a, const uint32_t* b) {
    asm volatile(
        "mma.sync.aligned.m16n8k16.row.col.f32.bf16.bf16.f32 "
        "{%0,%1,%2,%3}, {%4,%5,%6,%7}, {%8,%9}, {%0,%1,%2,%3};"
        : "+f"(c[0]), "+f"(c[1]), "+f"(c[2]), "+f"(c[3])
        : "r"(a[0]), "r"(a[1]), "r"(a[2]), "r"(a[3]), "r"(b[0]), "r"(b[1]));
}

__device__ __forceinline__ void split_bf16(float a, __nv_bfloat16& hi, __nv_bfloat16& lo) {
    hi = __float2bfloat16_rn(a);
    lo = __float2bfloat16_rn(a - __bfloat162float(hi));
}
__device__ __forceinline__ uint32_t pack_bf16(__nv_bfloat16 x0, __nv_bfloat16 x1) {
    return ((uint32_t)__bfloat16_as_ushort(x1) << 16) | (uint32_t)__bfloat16_as_ushort(x0);
}

// ---------------- CSR construction ----------------
__global__ void zero_cursor_kernel() {
    int i = blockIdx.x * blockDim.x + threadIdx.x;
    if (i < NN) g_cursor[i] = 0;
}
__global__ void hist_kernel(const int* __restrict__ row) {
    int e = blockIdx.x * blockDim.x + threadIdx.x;
    if (e < EE) atomicAdd(&g_cursor[row[e]], 1);
}
__global__ void scan_kernel() {
    __shared__ int s[1024];
    int t = threadIdx.x;
    int base = t * 64;
    int sum = 0;
#pragma unroll 8
    for (int i = 0; i < 64; i++) sum += g_cursor[base + i];
    s[t] = sum;
    __syncthreads();
    for (int off = 1; off < 1024; off <<= 1) {
        int v = (t >= off) ? s[t - off] : 0;
        __syncthreads();
        s[t] += v;
        __syncthreads();
    }
    int running = s[t] - sum;
    for (int i = 0; i < 64; i++) {
        int d = g_cursor[base + i];
        g_rowoff[base + i] = running;
        g_cursor[base + i] = running;
        running += d;
    }
    if (t == 1023) g_rowoff[NN] = s[1023];
}
__global__ void scatter_kernel(const int* __restrict__ row, const int* __restrict__ col,
                               const float* __restrict__ w) {
    int e = blockIdx.x * blockDim.x + threadIdx.x;
    if (e < EE) {
        int p = atomicAdd(&g_cursor[row[e]], 1);
        g_edge[p] = make_int2(col[e], __float_as_int(w[e]));
    }
}

// ---------------- weight transpose + pad + bf16 split ----------------
__global__ void splitw_kernel(const float* __restrict__ W,
                              __nv_bfloat16* __restrict__ Bh, __nv_bfloat16* __restrict__ Bl,
                              int K, int N, int Kpad) {
    int idx = blockIdx.x * blockDim.x + threadIdx.x;
    if (idx >= N * Kpad) return;
    int n = idx / Kpad, k = idx - n * Kpad;
    float v = (k < K) ? W[(size_t)k * N + n] : 0.f;
    __nv_bfloat16 hi, lo;
    split_bf16(v, hi, lo);
    Bh[idx] = hi;
    Bl[idx] = lo;
}

// ---------------- bf16-split mma.sync GEMM, 3-stage pipeline, 1 sync/chunk ----------------
// CTA tile 128x64, BK=32, 8 warps 4(m)x2(n), warp tile 32x32.
#define SM_AH   0
#define SM_AL   10240
#define SM_BH   20480
#define SM_BL   25600
#define SM_BUF  30720
#define GEMM_SMEM (3 * SM_BUF)

template <int N_, bool RELU>
__global__ void __launch_bounds__(256, 2) gemm_mma_kernel(
    const float* __restrict__ A, const __nv_bfloat16* __restrict__ Bh,
    const __nv_bfloat16* __restrict__ Bl, const float* __restrict__ bias,
    float* __restrict__ C, int K, int Kpad)
{
    extern __shared__ char smem[];
    uint32_t sbase = smem_to_u32(smem);

    int tid  = threadIdx.x;
    int wid  = tid >> 5;
    int lane = tid & 31;
    int m0 = blockIdx.x * 128;
    int n0 = blockIdx.y * 64;
    int warp_m = wid & 3;
    int warp_n = wid >> 2;

    float acc[2][4][4];
#pragma unroll
    for (int i = 0; i < 2; i++)
#pragma unroll
        for (int j = 0; j < 4; j++)
#pragma unroll
            for (int r = 0; r < 4; r++) acc[i][j][r] = 0.f;

    const int nch = Kpad >> 5;

    float4 ga[4];
    uint4  gbh, gbl;

    int a_row[4], a_col[4];
#pragma unroll
    for (int i = 0; i < 4; i++) {
        int slot = tid + i * 256;
        a_row[i] = slot >> 3;
        a_col[i] = (slot & 7) * 4;
    }
    int b_row = tid >> 2;
    int b_seg = tid & 3;

#define LOAD_GLOBAL(CH) do { \
    int k0_ = (CH) << 5; \
    _Pragma("unroll") \
    for (int i = 0; i < 4; i++) { \
        int kg = k0_ + a_col[i]; \
        if (kg < K) ga[i] = *(const float4*)(A + (size_t)(m0 + a_row[i]) * K + kg); \
        else        ga[i] = make_float4(0.f, 0.f, 0.f, 0.f); \
    } \
    { \
        const __nv_bfloat16* ph = Bh + (size_t)(n0 + b_row) * Kpad + k0_ + b_seg * 8; \
        const __nv_bfloat16* pl = Bl + (size_t)(n0 + b_row) * Kpad + k0_ + b_seg * 8; \
        gbh = *(const uint4*)ph; \
        gbl = *(const uint4*)pl; \
    } \
} while (0)

#define STORE_SMEM(BUF) do { \
    char* tb = smem + (BUF) * SM_BUF; \
    _Pragma("unroll") \
    for (int i = 0; i < 4; i++) { \
        __nv_bfloat16 hx, lx, hy, ly, hz, lz, hw, lw; \
        split_bf16(ga[i].x, hx, lx); split_bf16(ga[i].y, hy, ly); \
        split_bf16(ga[i].z, hz, lz); split_bf16(ga[i].w, hw, lw); \
        uint2 ph_ = make_uint2(pack_bf16(hx, hy), pack_bf16(hz, hw)); \
        uint2 pl_ = make_uint2(pack_bf16(lx, ly), pack_bf16(lz, lw)); \
        int off = a_row[i] * 80 + a_col[i] * 2; \
        *(uint2*)(tb + SM_AH + off) = ph_; \
        *(uint2*)(tb + SM_AL + off) = pl_; \
    } \
    { \
        int off = b_row * 80 + b_seg * 16; \
        *(uint4*)(tb + SM_BH + off) = gbh; \
        *(uint4*)(tb + SM_BL + off) = gbl; \
    } \
} while (0)

    // prologue: stage chunk 0 into smem buf 0, chunk 1 into regs
    LOAD_GLOBAL(0);
    STORE_SMEM(0);
    if (nch > 1) LOAD_GLOBAL(1);
    __syncthreads();

    int sbuf = 0;   // buffer holding chunk ch
    for (int ch = 0; ch < nch; ch++) {
        // regs hold chunk ch+1: store to the dead buffer (last computed at ch-2)
        int nbuf = (sbuf == 2) ? 0 : sbuf + 1;
        if (ch + 1 < nch) STORE_SMEM(nbuf);
        // issue global loads for chunk ch+2 early (overlap with compute below)
        if (ch + 2 < nch) LOAD_GLOBAL(ch + 2);

        // ---- compute chunk ch from smem[sbuf] ----
        uint32_t ub = sbase + sbuf * SM_BUF;
#pragma unroll
        for (int kk = 0; kk < 32; kk += 16) {
            uint32_t afr[2][2][4];
            uint32_t bfr[2][2][4];
            {
                int rowA = warp_m * 32 + (lane & 15);
                int colA = kk + ((lane >> 4) << 3);
#pragma unroll
                for (int mt = 0; mt < 2; mt++) {
                    uint32_t ad = ub + (uint32_t)((rowA + mt * 16) * 80 + colA * 2);
                    ldmatrix_x4(afr[0][mt], ad + SM_AH);
                    ldmatrix_x4(afr[1][mt], ad + SM_AL);
                }
                int rowB = warp_n * 32 + ((lane >> 4) << 3) + (lane & 7);
                int colB = kk + (((lane >> 3) & 1) << 3);
#pragma unroll
                for (int np = 0; np < 2; np++) {
                    uint32_t bd = ub + (uint32_t)((rowB + np * 16) * 80 + colB * 2);
                    ldmatrix_x4(bfr[0][np], bd + SM_BH);
                    ldmatrix_x4(bfr[1][np], bd + SM_BL);
                }
            }
#pragma unroll
            for (int mt = 0; mt < 2; mt++)
#pragma unroll
                for (int nt = 0; nt < 4; nt++) {
                    int np = nt >> 1, sub = (nt & 1) * 2;
                    mma_bf16(acc[mt][nt], afr[0][mt], &bfr[0][np][sub]);
                    mma_bf16(acc[mt][nt], afr[0][mt], &bfr[1][np][sub]);
                    mma_bf16(acc[mt][nt], afr[1][mt], &bfr[0][np][sub]);
                }
        }
        __syncthreads();
        sbuf = nbuf;
    }

    int rb   = m0 + warp_m * 32 + (lane >> 2);
    int colb = n0 + warp_n * 32 + (lane & 3) * 2;
#pragma unroll
    for (int mt = 0; mt < 2; mt++)
#pragma unroll
        for (int nt = 0; nt < 4; nt++) {
            float b0 = __ldg(bias + colb + nt * 8);
            float b1 = __ldg(bias + colb + nt * 8 + 1);
#pragma unroll
            for (int r = 0; r < 4; r++) {
                int row = rb + mt * 16 + ((r >> 1) << 3);
                int col = colb + nt * 8 + (r & 1);
                float v = acc[mt][nt][r] + ((r & 1) ? b1 : b0);
                if (RELU) v = fmaxf(v, 0.f);
                C[(size_t)row * N_ + col] = v;
            }
        }
}

// ---------------- propagation: warp = row, two 16-lane halves, pipelined edge loads ----------------
__global__ void __launch_bounds__(256) prop_kernel(
    const float* __restrict__ hsrc, const float* __restrict__ h0,
    float* __restrict__ hdst)
{
    int warp = (blockIdx.x * blockDim.x + threadIdx.x) >> 5;
    if (warp >= NN) return;
    int lane = threadIdx.x & 31;
    int half = lane >> 4;          // 0/1: alternate edges
    int sub  = lane & 15;          // channel group: 4 floats each

    int beg = g_rowoff[warp];
    int end = g_rowoff[warp + 1];

    float4 acc = make_float4(0.f, 0.f, 0.f, 0.f);
    int idx = beg + half;
    if (idx < end) {
        int2 ed = __ldg(&g_edge[idx]);
        while (true) {
            int nidx = idx + 2;
            int2 edn;
            bool more = (nidx < end);
            if (more) edn = __ldg(&g_edge[nidx]);      // prefetch next edge
            float w = __int_as_float(ed.y);
            float4 hv = *(const float4*)(hsrc + (size_t)ed.x * OUTD + sub * 4);
            acc.x = fmaf(hv.x, w, acc.x);
            acc.y = fmaf(hv.y, w, acc.y);
            acc.z = fmaf(hv.z, w, acc.z);
            acc.w = fmaf(hv.w, w, acc.w);
            if (!more) break;
            ed = edn;
            idx = nidx;
        }
    }
    __syncwarp();
    acc.x += __shfl_down_sync(0xffffffffu, acc.x, 16);
    acc.y += __shfl_down_sync(0xffffffffu, acc.y, 16);
    acc.z += __shfl_down_sync(0xffffffffu, acc.z, 16);
    acc.w += __shfl_down_sync(0xffffffffu, acc.w, 16);

    if (half == 0) {
        float4 h0v = *(const float4*)(h0 + (size_t)warp * OUTD + sub * 4);
        float4 outv;
        outv.x = (1.0f - ALPHA) * acc.x + ALPHA * h0v.x;
        outv.y = (1.0f - ALPHA) * acc.y + ALPHA * h0v.y;
        outv.z = (1.0f - ALPHA) * acc.z + ALPHA * h0v.z;
        outv.w = (1.0f - ALPHA) * acc.w + ALPHA * h0v.w;
        *(float4*)(hdst + (size_t)warp * OUTD + sub * 4) = outv;
    }
}

// ---------------- host launcher ----------------
extern "C" void kernel_launch(void* const* d_in, const int* in_sizes, int n_in,
                              void* d_out, int out_size)
{
    const float* x    = (const float*)d_in[0];
    const float* W1   = (const float*)d_in[1];
    const float* b1   = (const float*)d_in[2];
    const float* W2   = (const float*)d_in[3];
    const float* b2   = (const float*)d_in[4];
    const float* W3   = (const float*)d_in[5];
    const float* b3   = (const float*)d_in[6];
    const float* ew   = (const float*)d_in[7];
    const int*   erow = (const int*)d_in[8];
    const int*   ecol = (const int*)d_in[9];

    float *h1, *h2, *h0, *hA, *hB;
    __nv_bfloat16 *b1h, *b1l, *b2h, *b2l, *b3h, *b3l;
    cudaGetSymbolAddress((void**)&h1, g_h1);
    cudaGetSymbolAddress((void**)&h2, g_h2);
    cudaGetSymbolAddress((void**)&h0, g_h0);
    cudaGetSymbolAddress((void**)&hA, g_hA);
    cudaGetSymbolAddress((void**)&hB, g_hB);
    cudaGetSymbolAddress((void**)&b1h, g_B1h);
    cudaGetSymbolAddress((void**)&b1l, g_B1l);
    cudaGetSymbolAddress((void**)&b2h, g_B2h);
    cudaGetSymbolAddress((void**)&b2l, g_B2l);
    cudaGetSymbolAddress((void**)&b3h, g_B3h);
    cudaGetSymbolAddress((void**)&b3l, g_B3l);

    cudaFuncSetAttribute(gemm_mma_kernel<256, true >, cudaFuncAttributeMaxDynamicSharedMemorySize, GEMM_SMEM);
    cudaFuncSetAttribute(gemm_mma_kernel<64,  false>, cudaFuncAttributeMaxDynamicSharedMemorySize, GEMM_SMEM);

    // CSR build
    zero_cursor_kernel<<<NN / 256, 256>>>();
    hist_kernel<<<EE / 256, 256>>>(erow);
    scan_kernel<<<1, 1024>>>();
    scatter_kernel<<<EE / 256, 256>>>(erow, ecol, ew);

    // weight transpose + split
    splitw_kernel<<<(HID * KPAD1 + 255) / 256, 256>>>(W1, b1h, b1l, IN_DIM, HID, KPAD1);
    splitw_kernel<<<(HID * HID + 255) / 256, 256>>>(W2, b2h, b2l, HID, HID, HID);
    splitw_kernel<<<(OUTD * HID + 255) / 256, 256>>>(W3, b3h, b3l, HID, OUTD, HID);

    // MLP on tensor cores (bf16 2-term split, fp32 accumulate)
    gemm_mma_kernel<256, true ><<<dim3(NN / 128, 4), 256, GEMM_SMEM>>>(x,  b1h, b1l, b1, h1, IN_DIM, KPAD1);
    gemm_mma_kernel<256, true ><<<dim3(NN / 128, 4), 256, GEMM_SMEM>>>(h1, b2h, b2l, b2, h2, HID, HID);
    gemm_mma_kernel<64,  false><<<dim3(NN / 128, 1), 256, GEMM_SMEM>>>(h2, b3h, b3l, b3, h0, HID, HID);

    // K=10 propagation steps
    float* out = (float*)d_out;
    const float* src = h0;
    for (int s = 0; s < 10; s++) {
        float* dst = (s == 9) ? out : ((s & 1) ? hB : hA);
        prop_kernel<<<(NN * 32) / 256, 256>>>(src, h0, dst);
        src = dst;
    }
}

// round 6
// speedup vs baseline: 1.0087x; 1.0087x over previous
#include <cuda_runtime.h>
#include <cuda_bf16.h>
#include <cstdint>

#define NN      65536
#define EE      1048576
#define IN_DIM  500
#define KPAD1   512
#define HID     256
#define OUTD    64
#define ALPHA   0.1f

// ---------------- static device scratch ----------------
__device__ float g_h1[(size_t)NN * HID];
__device__ float g_h2[(size_t)NN * HID];
__device__ float g_h0[(size_t)NN * OUTD];
__device__ float g_hA[(size_t)NN * OUTD];
__device__ float g_hB[(size_t)NN * OUTD];
__device__ __nv_bfloat16 g_B1h[(size_t)HID * KPAD1];
__device__ __nv_bfloat16 g_B1l[(size_t)HID * KPAD1];
__device__ __nv_bfloat16 g_B2h[(size_t)HID * HID];
__device__ __nv_bfloat16 g_B2l[(size_t)HID * HID];
__device__ __nv_bfloat16 g_B3h[(size_t)OUTD * HID];
__device__ __nv_bfloat16 g_B3l[(size_t)OUTD * HID];
__device__ int   g_rowoff[NN + 1];
__device__ int   g_cursor[NN];
__device__ int2  g_edge[EE];     // (col, 0.9*weight bits)

// ---------------- helpers ----------------
__device__ __forceinline__ uint32_t smem_to_u32(const void* p) {
    uint32_t a;
    asm("{ .reg .u64 t; cvta.to.shared.u64 t, %1; cvt.u32.u64 %0, t; }" : "=r"(a) : "l"(p));
    return a;
}

__device__ __forceinline__ void ldmatrix_x4(uint32_t* r, uint32_t addr) {
    asm volatile("ldmatrix.sync.aligned.m8n8.x4.shared.b16 {%0,%1,%2,%3}, [%4];"
                 : "=r"(r[0]), "=r"(r[1]), "=r"(r[2]), "=r"(r[3]) : "r"(addr));
}

__device__ __forceinline__ void mma_bf16(float* c, const uint32_t* a, const uint32_t* b) {
    asm volatile(
        "mma.sync.aligned.m16n8k16.row.col.f32.bf16.bf16.f32 "
        "{%0,%1,%2,%3}, {%4,%5,%6,%7}, {%8,%9}, {%0,%1,%2,%3};"
        : "+f"(c[0]), "+f"(c[1]), "+f"(c[2]), "+f"(c[3])
        : "r"(a[0]), "r"(a[1]), "r"(a[2]), "r"(a[3]), "r"(b[0]), "r"(b[1]));
}

__device__ __forceinline__ void split_bf16(float a, __nv_bfloat16& hi, __nv_bfloat16& lo) {
    hi = __float2bfloat16_rn(a);
    lo = __float2bfloat16_rn(a - __bfloat162float(hi));
}
__device__ __forceinline__ uint32_t pack_bf16(__nv_bfloat16 x0, __nv_bfloat16 x1) {
    return ((uint32_t)__bfloat16_as_ushort(x1) << 16) | (uint32_t)__bfloat16_as_ushort(x0);
}

// ---------------- CSR construction ----------------
__global__ void zero_cursor_kernel() {
    int i = blockIdx.x * blockDim.x + threadIdx.x;
    if (i < NN) g_cursor[i] = 0;
}
__global__ void hist_kernel(const int* __restrict__ row) {
    int e = blockIdx.x * blockDim.x + threadIdx.x;
    if (e < EE) atomicAdd(&g_cursor[row[e]], 1);
}
__global__ void scan_kernel() {
    __shared__ int s[1024];
    int t = threadIdx.x;
    int base = t * 64;
    int sum = 0;
#pragma unroll 8
    for (int i = 0; i < 64; i++) sum += g_cursor[base + i];
    s[t] = sum;
    __syncthreads();
    for (int off = 1; off < 1024; off <<= 1) {
        int v = (t >= off) ? s[t - off] : 0;
        __syncthreads();
        s[t] += v;
        __syncthreads();
    }
    int running = s[t] - sum;
    for (int i = 0; i < 64; i++) {
        int d = g_cursor[base + i];
        g_rowoff[base + i] = running;
        g_cursor[base + i] = running;
        running += d;
    }
    if (t == 1023) g_rowoff[NN] = s[1023];
}
__global__ void scatter_kernel(const int* __restrict__ row, const int* __restrict__ col,
                               const float* __restrict__ w) {
    int e = blockIdx.x * blockDim.x + threadIdx.x;
    if (e < EE) {
        int p = atomicAdd(&g_cursor[row[e]], 1);
        g_edge[p] = make_int2(col[e], __float_as_int(0.9f * w[e]));  // fold (1-ALPHA)
    }
}

// ---------------- weight transpose + pad + bf16 split ----------------
__global__ void splitw_kernel(const float* __restrict__ W,
                              __nv_bfloat16* __restrict__ Bh, __nv_bfloat16* __restrict__ Bl,
                              int K, int N, int Kpad) {
    int idx = blockIdx.x * blockDim.x + threadIdx.x;
    if (idx >= N * Kpad) return;
    int n = idx / Kpad, k = idx - n * Kpad;
    float v = (k < K) ? W[(size_t)k * N + n] : 0.f;
    __nv_bfloat16 hi, lo;
    split_bf16(v, hi, lo);
    Bh[idx] = hi;
    Bl[idx] = lo;
}

// ---------------- bf16-split mma.sync GEMM (round-4 structure, grid swapped) ----------------
// CTA tile 128x64, BK=32, 8 warps 4(m)x2(n), warp tile 32x32. Double-buffered.
// grid = (n_tiles, m_tiles): CTAs sharing an A m-tile are consecutive -> L2 dedup.
#define SM_AH   0
#define SM_AL   10240
#define SM_BH   20480
#define SM_BL   25600
#define SM_BUF  30720
#define GEMM_SMEM (2 * SM_BUF)

template <int N_, bool RELU>
__global__ void __launch_bounds__(256, 2) gemm_mma_kernel(
    const float* __restrict__ A, const __nv_bfloat16* __restrict__ Bh,
    const __nv_bfloat16* __restrict__ Bl, const float* __restrict__ bias,
    float* __restrict__ C, int K, int Kpad)
{
    extern __shared__ char smem[];
    uint32_t sbase = smem_to_u32(smem);

    int tid  = threadIdx.x;
    int wid  = tid >> 5;
    int lane = tid & 31;
    int m0 = blockIdx.y * 128;    // swapped: y = m-tile
    int n0 = blockIdx.x * 64;     // swapped: x = n-tile (consecutive share A)
    int warp_m = wid & 3;
    int warp_n = wid >> 2;

    float acc[2][4][4];
#pragma unroll
    for (int i = 0; i < 2; i++)
#pragma unroll
        for (int j = 0; j < 4; j++)
#pragma unroll
            for (int r = 0; r < 4; r++) acc[i][j][r] = 0.f;

    const int nch = Kpad >> 5;

    float4 ga[4];
    uint4  gbh, gbl;

    int a_row[4], a_col[4];
#pragma unroll
    for (int i = 0; i < 4; i++) {
        int slot = tid + i * 256;
        a_row[i] = slot >> 3;
        a_col[i] = (slot & 7) * 4;
    }
    int b_row = tid >> 2;
    int b_seg = tid & 3;

#define LOAD_GLOBAL(CH) do { \
    int k0_ = (CH) << 5; \
    _Pragma("unroll") \
    for (int i = 0; i < 4; i++) { \
        int kg = k0_ + a_col[i]; \
        if (kg < K) ga[i] = *(const float4*)(A + (size_t)(m0 + a_row[i]) * K + kg); \
        else        ga[i] = make_float4(0.f, 0.f, 0.f, 0.f); \
    } \
    { \
        const __nv_bfloat16* ph = Bh + (size_t)(n0 + b_row) * Kpad + k0_ + b_seg * 8; \
        const __nv_bfloat16* pl = Bl + (size_t)(n0 + b_row) * Kpad + k0_ + b_seg * 8; \
        gbh = *(const uint4*)ph; \
        gbl = *(const uint4*)pl; \
    } \
} while (0)

#define STORE_SMEM(BUF) do { \
    char* tb = smem + (BUF) * SM_BUF; \
    _Pragma("unroll") \
    for (int i = 0; i < 4; i++) { \
        __nv_bfloat16 hx, lx, hy, ly, hz, lz, hw, lw; \
        split_bf16(ga[i].x, hx, lx); split_bf16(ga[i].y, hy, ly); \
        split_bf16(ga[i].z, hz, lz); split_bf16(ga[i].w, hw, lw); \
        uint2 ph_ = make_uint2(pack_bf16(hx, hy), pack_bf16(hz, hw)); \
        uint2 pl_ = make_uint2(pack_bf16(lx, ly), pack_bf16(lz, lw)); \
        int off = a_row[i] * 80 + a_col[i] * 2; \
        *(uint2*)(tb + SM_AH + off) = ph_; \
        *(uint2*)(tb + SM_AL + off) = pl_; \
    } \
    { \
        int off = b_row * 80 + b_seg * 16; \
        *(uint4*)(tb + SM_BH + off) = gbh; \
        *(uint4*)(tb + SM_BL + off) = gbl; \
    } \
} while (0)

    LOAD_GLOBAL(0);
    STORE_SMEM(0);
    __syncthreads();

    for (int ch = 0; ch < nch; ch++) {
        if (ch + 1 < nch) LOAD_GLOBAL(ch + 1);

        uint32_t ub = sbase + (ch & 1) * SM_BUF;
#pragma unroll
        for (int kk = 0; kk < 32; kk += 16) {
            uint32_t afr[2][2][4];
            uint32_t bfr[2][2][4];
            {
                int rowA = warp_m * 32 + (lane & 15);
                int colA = kk + ((lane >> 4) << 3);
#pragma unroll
                for (int mt = 0; mt < 2; mt++) {
                    uint32_t ad = ub + (uint32_t)((rowA + mt * 16) * 80 + colA * 2);
                    ldmatrix_x4(afr[0][mt], ad + SM_AH);
                    ldmatrix_x4(afr[1][mt], ad + SM_AL);
                }
                int rowB = warp_n * 32 + ((lane >> 4) << 3) + (lane & 7);
                int colB = kk + (((lane >> 3) & 1) << 3);
#pragma unroll
                for (int np = 0; np < 2; np++) {
                    uint32_t bd = ub + (uint32_t)((rowB + np * 16) * 80 + colB * 2);
                    ldmatrix_x4(bfr[0][np], bd + SM_BH);
                    ldmatrix_x4(bfr[1][np], bd + SM_BL);
                }
            }
#pragma unroll
            for (int mt = 0; mt < 2; mt++)
#pragma unroll
                for (int nt = 0; nt < 4; nt++) {
                    int np = nt >> 1, sub = (nt & 1) * 2;
                    mma_bf16(acc[mt][nt], afr[0][mt], &bfr[0][np][sub]);
                    mma_bf16(acc[mt][nt], afr[0][mt], &bfr[1][np][sub]);
                    mma_bf16(acc[mt][nt], afr[1][mt], &bfr[0][np][sub]);
                }
        }
        __syncthreads();
        if (ch + 1 < nch) {
            STORE_SMEM((ch + 1) & 1);
        }
        __syncthreads();
    }

    int rb   = m0 + warp_m * 32 + (lane >> 2);
    int colb = n0 + warp_n * 32 + (lane & 3) * 2;
#pragma unroll
    for (int mt = 0; mt < 2; mt++)
#pragma unroll
        for (int nt = 0; nt < 4; nt++) {
            float b0 = __ldg(bias + colb + nt * 8);
            float b1 = __ldg(bias + colb + nt * 8 + 1);
#pragma unroll
            for (int r = 0; r < 4; r++) {
                int row = rb + mt * 16 + ((r >> 1) << 3);
                int col = colb + nt * 8 + (r & 1);
                float v = acc[mt][nt][r] + ((r & 1) ? b1 : b0);
                if (RELU) v = fmaxf(v, 0.f);
                C[(size_t)row * N_ + col] = v;
            }
        }
}

// ---------------- propagation: warp = row, two 16-lane halves, pipelined edge loads ----------------
// hdst[r] = sum_e h[col(e)]*(0.9*w(e)) + 0.1 * h0[r]   (0.9 pre-folded into edge weight)
__global__ void __launch_bounds__(256) prop_kernel(
    const float* __restrict__ hsrc, const float* __restrict__ h0,
    float* __restrict__ hdst)
{
    int warp = (blockIdx.x * blockDim.x + threadIdx.x) >> 5;
    if (warp >= NN) return;
    int lane = threadIdx.x & 31;
    int half = lane >> 4;
    int sub  = lane & 15;

    int beg = g_rowoff[warp];
    int end = g_rowoff[warp + 1];

    float4 acc = make_float4(0.f, 0.f, 0.f, 0.f);
    int idx = beg + half;
    if (idx < end) {
        int2 ed = __ldg(&g_edge[idx]);
        while (true) {
            int nidx = idx + 2;
            int2 edn;
            bool more = (nidx < end);
            if (more) edn = __ldg(&g_edge[nidx]);
            float w = __int_as_float(ed.y);
            float4 hv = *(const float4*)(hsrc + (size_t)ed.x * OUTD + sub * 4);
            acc.x = fmaf(hv.x, w, acc.x);
            acc.y = fmaf(hv.y, w, acc.y);
            acc.z = fmaf(hv.z, w, acc.z);
            acc.w = fmaf(hv.w, w, acc.w);
            if (!more) break;
            ed = edn;
            idx = nidx;
        }
    }
    __syncwarp();
    acc.x += __shfl_down_sync(0xffffffffu, acc.x, 16);
    acc.y += __shfl_down_sync(0xffffffffu, acc.y, 16);
    acc.z += __shfl_down_sync(0xffffffffu, acc.z, 16);
    acc.w += __shfl_down_sync(0xffffffffu, acc.w, 16);

    if (half == 0) {
        float4 h0v = *(const float4*)(h0 + (size_t)warp * OUTD + sub * 4);
        float4 outv;
        outv.x = acc.x + ALPHA * h0v.x;
        outv.y = acc.y + ALPHA * h0v.y;
        outv.z = acc.z + ALPHA * h0v.z;
        outv.w = acc.w + ALPHA * h0v.w;
        *(float4*)(hdst + (size_t)warp * OUTD + sub * 4) = outv;
    }
}

// ---------------- host launcher ----------------
extern "C" void kernel_launch(void* const* d_in, const int* in_sizes, int n_in,
                              void* d_out, int out_size)
{
    const float* x    = (const float*)d_in[0];
    const float* W1   = (const float*)d_in[1];
    const float* b1   = (const float*)d_in[2];
    const float* W2   = (const float*)d_in[3];
    const float* b2   = (const float*)d_in[4];
    const float* W3   = (const float*)d_in[5];
    const float* b3   = (const float*)d_in[6];
    const float* ew   = (const float*)d_in[7];
    const int*   erow = (const int*)d_in[8];
    const int*   ecol = (const int*)d_in[9];

    float *h1, *h2, *h0, *hA, *hB;
    __nv_bfloat16 *b1h, *b1l, *b2h, *b2l, *b3h, *b3l;
    cudaGetSymbolAddress((void**)&h1, g_h1);
    cudaGetSymbolAddress((void**)&h2, g_h2);
    cudaGetSymbolAddress((void**)&h0, g_h0);
    cudaGetSymbolAddress((void**)&hA, g_hA);
    cudaGetSymbolAddress((void**)&hB, g_hB);
    cudaGetSymbolAddress((void**)&b1h, g_B1h);
    cudaGetSymbolAddress((void**)&b1l, g_B1l);
    cudaGetSymbolAddress((void**)&b2h, g_B2h);
    cudaGetSymbolAddress((void**)&b2l, g_B2l);
    cudaGetSymbolAddress((void**)&b3h, g_B3h);
    cudaGetSymbolAddress((void**)&b3l, g_B3l);

    cudaFuncSetAttribute(gemm_mma_kernel<256, true >, cudaFuncAttributeMaxDynamicSharedMemorySize, GEMM_SMEM);
    cudaFuncSetAttribute(gemm_mma_kernel<64,  false>, cudaFuncAttributeMaxDynamicSharedMemorySize, GEMM_SMEM);

    // CSR build
    zero_cursor_kernel<<<NN / 256, 256>>>();
    hist_kernel<<<EE / 256, 256>>>(erow);
    scan_kernel<<<1, 1024>>>();
    scatter_kernel<<<EE / 256, 256>>>(erow, ecol, ew);

    // weight transpose + split
    splitw_kernel<<<(HID * KPAD1 + 255) / 256, 256>>>(W1, b1h, b1l, IN_DIM, HID, KPAD1);
    splitw_kernel<<<(HID * HID + 255) / 256, 256>>>(W2, b2h, b2l, HID, HID, HID);
    splitw_kernel<<<(OUTD * HID + 255) / 256, 256>>>(W3, b3h, b3l, HID, OUTD, HID);

    // MLP on tensor cores (bf16 2-term split, fp32 accumulate)
    // grid = (n_tiles, m_tiles): consecutive CTAs share the A m-tile via L2
    gemm_mma_kernel<256, true ><<<dim3(4, NN / 128), 256, GEMM_SMEM>>>(x,  b1h, b1l, b1, h1, IN_DIM, KPAD1);
    gemm_mma_kernel<256, true ><<<dim3(4, NN / 128), 256, GEMM_SMEM>>>(h1, b2h, b2l, b2, h2, HID, HID);
    gemm_mma_kernel<64,  false><<<dim3(1, NN / 128), 256, GEMM_SMEM>>>(h2, b3h, b3l, b3, h0, HID, HID);

    // K=10 propagation steps
    float* out = (float*)d_out;
    const float* src = h0;
    for (int s = 0; s < 10; s++) {
        float* dst = (s == 9) ? out : ((s & 1) ? hB : hA);
        prop_kernel<<<(NN * 32) / 256, 256>>>(src, h0, dst);
        src = dst;
    }
}

// round 7
// speedup vs baseline: 1.0226x; 1.0137x over previous
#include <cuda_runtime.h>
#include <cuda_bf16.h>
#include <cstdint>

#define NN      65536
#define EE      1048576
#define IN_DIM  500
#define KPAD1   512
#define HID     256
#define OUTD    64
#define ALPHA   0.1f

// ---------------- static device scratch ----------------
__device__ __nv_bfloat16 g_h1h[(size_t)NN * HID];   // layer-1 out, bf16 hi
__device__ __nv_bfloat16 g_h1l[(size_t)NN * HID];   // layer-1 out, bf16 lo
__device__ __nv_bfloat16 g_h2h[(size_t)NN * HID];
__device__ __nv_bfloat16 g_h2l[(size_t)NN * HID];
__device__ float g_h0[(size_t)NN * OUTD];
__device__ float g_hA[(size_t)NN * OUTD];
__device__ float g_hB[(size_t)NN * OUTD];
__device__ __nv_bfloat16 g_B1h[(size_t)HID * KPAD1];
__device__ __nv_bfloat16 g_B1l[(size_t)HID * KPAD1];
__device__ __nv_bfloat16 g_B2h[(size_t)HID * HID];
__device__ __nv_bfloat16 g_B2l[(size_t)HID * HID];
__device__ __nv_bfloat16 g_B3h[(size_t)OUTD * HID];
__device__ __nv_bfloat16 g_B3l[(size_t)OUTD * HID];
__device__ int   g_rowoff[NN + 1];
__device__ int   g_cursor[NN];
__device__ int2  g_edge[EE];     // (col, 0.9*weight bits)

// ---------------- helpers ----------------
__device__ __forceinline__ uint32_t smem_to_u32(const void* p) {
    uint32_t a;
    asm("{ .reg .u64 t; cvta.to.shared.u64 t, %1; cvt.u32.u64 %0, t; }" : "=r"(a) : "l"(p));
    return a;
}

__device__ __forceinline__ void ldmatrix_x4(uint32_t* r, uint32_t addr) {
    asm volatile("ldmatrix.sync.aligned.m8n8.x4.shared.b16 {%0,%1,%2,%3}, [%4];"
                 : "=r"(r[0]), "=r"(r[1]), "=r"(r[2]), "=r"(r[3]) : "r"(addr));
}

__device__ __forceinline__ void mma_bf16(float* c, const uint32_t* a, const uint32_t* b) {
    asm volatile(
        "mma.sync.aligned.m16n8k16.row.col.f32.bf16.bf16.f32 "
        "{%0,%1,%2,%3}, {%4,%5,%6,%7}, {%8,%9}, {%0,%1,%2,%3};"
        : "+f"(c[0]), "+f"(c[1]), "+f"(c[2]), "+f"(c[3])
        : "r"(a[0]), "r"(a[1]), "r"(a[2]), "r"(a[3]), "r"(b[0]), "r"(b[1]));
}

__device__ __forceinline__ void split_bf16(float a, __nv_bfloat16& hi, __nv_bfloat16& lo) {
    hi = __float2bfloat16_rn(a);
    lo = __float2bfloat16_rn(a - __bfloat162float(hi));
}
__device__ __forceinline__ uint32_t pack_bf16(__nv_bfloat16 x0, __nv_bfloat16 x1) {
    return ((uint32_t)__bfloat16_as_ushort(x1) << 16) | (uint32_t)__bfloat16_as_ushort(x0);
}

// ---------------- CSR construction ----------------
__global__ void zero_cursor_kernel() {
    int i = blockIdx.x * blockDim.x + threadIdx.x;
    if (i < NN) g_cursor[i] = 0;
}
__global__ void hist_kernel(const int* __restrict__ row) {
    int e = blockIdx.x * blockDim.x + threadIdx.x;
    if (e < EE) atomicAdd(&g_cursor[row[e]], 1);
}
__global__ void scan_kernel() {
    __shared__ int s[1024];
    int t = threadIdx.x;
    int base = t * 64;
    int sum = 0;
#pragma unroll 8
    for (int i = 0; i < 64; i++) sum += g_cursor[base + i];
    s[t] = sum;
    __syncthreads();
    for (int off = 1; off < 1024; off <<= 1) {
        int v = (t >= off) ? s[t - off] : 0;
        __syncthreads();
        s[t] += v;
        __syncthreads();
    }
    int running = s[t] - sum;
    for (int i = 0; i < 64; i++) {
        int d = g_cursor[base + i];
        g_rowoff[base + i] = running;
        g_cursor[base + i] = running;
        running += d;
    }
    if (t == 1023) g_rowoff[NN] = s[1023];
}
__global__ void scatter_kernel(const int* __restrict__ row, const int* __restrict__ col,
                               const float* __restrict__ w) {
    int e = blockIdx.x * blockDim.x + threadIdx.x;
    if (e < EE) {
        int p = atomicAdd(&g_cursor[row[e]], 1);
        g_edge[p] = make_int2(col[e], __float_as_int(0.9f * w[e]));  // fold (1-ALPHA)
    }
}

// ---------------- weight transpose + pad + bf16 split ----------------
__global__ void splitw_kernel(const float* __restrict__ W,
                              __nv_bfloat16* __restrict__ Bh, __nv_bfloat16* __restrict__ Bl,
                              int K, int N, int Kpad) {
    int idx = blockIdx.x * blockDim.x + threadIdx.x;
    if (idx >= N * Kpad) return;
    int n = idx / Kpad, k = idx - n * Kpad;
    float v = (k < K) ? W[(size_t)k * N + n] : 0.f;
    __nv_bfloat16 hi, lo;
    split_bf16(v, hi, lo);
    Bh[idx] = hi;
    Bl[idx] = lo;
}

// ---------------- bf16-split mma.sync GEMM (round-4 structure) ----------------
// CTA tile 128x64, BK=32, 8 warps 4(m)x2(n), warp tile 32x32. Double-buffered.
// A_SPLIT_IN: A supplied as pre-split bf16 hi/lo arrays (Ah, Al); else fp32 A, split on the fly.
// OUT_SPLIT:  write C as pre-split bf16 hi/lo (Ch, Cl); else fp32 C.
#define SM_AH   0
#define SM_AL   10240
#define SM_BH   20480
#define SM_BL   25600
#define SM_BUF  30720
#define GEMM_SMEM (2 * SM_BUF)

template <int N_, bool RELU, bool A_SPLIT_IN, bool OUT_SPLIT>
__global__ void __launch_bounds__(256, 2) gemm_mma_kernel(
    const float* __restrict__ A,
    const __nv_bfloat16* __restrict__ Ah, const __nv_bfloat16* __restrict__ Al,
    const __nv_bfloat16* __restrict__ Bh, const __nv_bfloat16* __restrict__ Bl,
    const float* __restrict__ bias,
    float* __restrict__ C,
    __nv_bfloat16* __restrict__ Ch, __nv_bfloat16* __restrict__ Cl,
    int K, int Kpad)
{
    extern __shared__ char smem[];
    uint32_t sbase = smem_to_u32(smem);

    int tid  = threadIdx.x;
    int wid  = tid >> 5;
    int lane = tid & 31;
    int m0 = blockIdx.x * 128;    // round-4 mapping: x = m-tile
    int n0 = blockIdx.y * 64;
    int warp_m = wid & 3;
    int warp_n = wid >> 2;

    float acc[2][4][4];
#pragma unroll
    for (int i = 0; i < 2; i++)
#pragma unroll
        for (int j = 0; j < 4; j++)
#pragma unroll
            for (int r = 0; r < 4; r++) acc[i][j][r] = 0.f;

    const int nch = Kpad >> 5;

    // staging regs
    float4 ga[4];          // fp32 A path
    uint4  gah[2], gal[2]; // pre-split A path
    uint4  gbh, gbl;

    // fp32-A slot mapping: 4 slots x float4 over 128x32
    int a_row[4], a_col[4];
#pragma unroll
    for (int i = 0; i < 4; i++) {
        int slot = tid + i * 256;
        a_row[i] = slot >> 3;
        a_col[i] = (slot & 7) * 4;
    }
    // split-A slot mapping: 2 slots x uint4(8 bf16) over 128x32
    int s_row[2], s_col[2];
#pragma unroll
    for (int i = 0; i < 2; i++) {
        int slot = tid + i * 256;
        s_row[i] = slot >> 2;
        s_col[i] = (slot & 3) * 8;
    }
    int b_row = tid >> 2;
    int b_seg = tid & 3;

#define LOAD_GLOBAL(CH) do { \
    int k0_ = (CH) << 5; \
    if (A_SPLIT_IN) { \
        _Pragma("unroll") \
        for (int i = 0; i < 2; i++) { \
            size_t off = (size_t)(m0 + s_row[i]) * Kpad + k0_ + s_col[i]; \
            gah[i] = *(const uint4*)(Ah + off); \
            gal[i] = *(const uint4*)(Al + off); \
        } \
    } else { \
        _Pragma("unroll") \
        for (int i = 0; i < 4; i++) { \
            int kg = k0_ + a_col[i]; \
            if (kg < K) ga[i] = *(const float4*)(A + (size_t)(m0 + a_row[i]) * K + kg); \
            else        ga[i] = make_float4(0.f, 0.f, 0.f, 0.f); \
        } \
    } \
    { \
        const __nv_bfloat16* ph = Bh + (size_t)(n0 + b_row) * Kpad + k0_ + b_seg * 8; \
        const __nv_bfloat16* pl = Bl + (size_t)(n0 + b_row) * Kpad + k0_ + b_seg * 8; \
        gbh = *(const uint4*)ph; \
        gbl = *(const uint4*)pl; \
    } \
} while (0)

#define STORE_SMEM(BUF) do { \
    char* tb = smem + (BUF) * SM_BUF; \
    if (A_SPLIT_IN) { \
        _Pragma("unroll") \
        for (int i = 0; i < 2; i++) { \
            int off = s_row[i] * 80 + s_col[i] * 2; \
            *(uint4*)(tb + SM_AH + off) = gah[i]; \
            *(uint4*)(tb + SM_AL + off) = gal[i]; \
        } \
    } else { \
        _Pragma("unroll") \
        for (int i = 0; i < 4; i++) { \
            __nv_bfloat16 hx, lx, hy, ly, hz, lz, hw, lw; \
            split_bf16(ga[i].x, hx, lx); split_bf16(ga[i].y, hy, ly); \
            split_bf16(ga[i].z, hz, lz); split_bf16(ga[i].w, hw, lw); \
            uint2 ph_ = make_uint2(pack_bf16(hx, hy), pack_bf16(hz, hw)); \
            uint2 pl_ = make_uint2(pack_bf16(lx, ly), pack_bf16(lz, lw)); \
            int off = a_row[i] * 80 + a_col[i] * 2; \
            *(uint2*)(tb + SM_AH + off) = ph_; \
            *(uint2*)(tb + SM_AL + off) = pl_; \
        } \
    } \
    { \
        int off = b_row * 80 + b_seg * 16; \
        *(uint4*)(tb + SM_BH + off) = gbh; \
        *(uint4*)(tb + SM_BL + off) = gbl; \
    } \
} while (0)

    LOAD_GLOBAL(0);
    STORE_SMEM(0);
    __syncthreads();

    for (int ch = 0; ch < nch; ch++) {
        if (ch + 1 < nch) LOAD_GLOBAL(ch + 1);

        uint32_t ub = sbase + (ch & 1) * SM_BUF;
#pragma unroll
        for (int kk = 0; kk < 32; kk += 16) {
            uint32_t afr[2][2][4];
            uint32_t bfr[2][2][4];
            {
                int rowA = warp_m * 32 + (lane & 15);
                int colA = kk + ((lane >> 4) << 3);
#pragma unroll
                for (int mt = 0; mt < 2; mt++) {
                    uint32_t ad = ub + (uint32_t)((rowA + mt * 16) * 80 + colA * 2);
                    ldmatrix_x4(afr[0][mt], ad + SM_AH);
                    ldmatrix_x4(afr[1][mt], ad + SM_AL);
                }
                int rowB = warp_n * 32 + ((lane >> 4) << 3) + (lane & 7);
                int colB = kk + (((lane >> 3) & 1) << 3);
#pragma unroll
                for (int np = 0; np < 2; np++) {
                    uint32_t bd = ub + (uint32_t)((rowB + np * 16) * 80 + colB * 2);
                    ldmatrix_x4(bfr[0][np], bd + SM_BH);
                    ldmatrix_x4(bfr[1][np], bd + SM_BL);
                }
            }
#pragma unroll
            for (int mt = 0; mt < 2; mt++)
#pragma unroll
                for (int nt = 0; nt < 4; nt++) {
                    int np = nt >> 1, sub = (nt & 1) * 2;
                    mma_bf16(acc[mt][nt], afr[0][mt], &bfr[0][np][sub]);
                    mma_bf16(acc[mt][nt], afr[0][mt], &bfr[1][np][sub]);
                    mma_bf16(acc[mt][nt], afr[1][mt], &bfr[0][np][sub]);
                }
        }
        __syncthreads();
        if (ch + 1 < nch) {
            STORE_SMEM((ch + 1) & 1);
        }
        __syncthreads();
    }

    // ---- epilogue ----
    // accumulator thread layout: row = lane>>2 (+8 per r-pair), cols = (lane&3)*2 + {0,1} adjacent
    int rb   = m0 + warp_m * 32 + (lane >> 2);
    int colb = n0 + warp_n * 32 + (lane & 3) * 2;
#pragma unroll
    for (int mt = 0; mt < 2; mt++)
#pragma unroll
        for (int nt = 0; nt < 4; nt++) {
            int col = colb + nt * 8;
            float b0 = __ldg(bias + col);
            float b1 = __ldg(bias + col + 1);
#pragma unroll
            for (int rp = 0; rp < 2; rp++) {       // r-pairs (0,1) and (2,3)
                int row = rb + mt * 16 + rp * 8;
                float v0 = acc[mt][nt][rp * 2 + 0] + b0;
                float v1 = acc[mt][nt][rp * 2 + 1] + b1;
                if (RELU) { v0 = fmaxf(v0, 0.f); v1 = fmaxf(v1, 0.f); }
                if (OUT_SPLIT) {
                    __nv_bfloat16 h0_, l0_, h1_, l1_;
                    split_bf16(v0, h0_, l0_);
                    split_bf16(v1, h1_, l1_);
                    size_t off = (size_t)row * N_ + col;
                    *(uint32_t*)(Ch + off) = pack_bf16(h0_, h1_);
                    *(uint32_t*)(Cl + off) = pack_bf16(l0_, l1_);
                } else {
                    size_t off = (size_t)row * N_ + col;
                    C[off]     = v0;
                    C[off + 1] = v1;
                }
            }
        }
}

// ---------------- propagation: round-4 structure, folded 0.9 weights ----------------
__global__ void __launch_bounds__(256) prop_kernel(
    const float* __restrict__ hsrc, const float* __restrict__ h0,
    float* __restrict__ hdst)
{
    int warp = (blockIdx.x * blockDim.x + threadIdx.x) >> 5;
    if (warp >= NN) return;
    int lane = threadIdx.x & 31;
    int half = lane >> 4;
    int sub  = lane & 15;

    int beg = g_rowoff[warp];
    int end = g_rowoff[warp + 1];

    float4 acc = make_float4(0.f, 0.f, 0.f, 0.f);
    for (int idx = beg + half; idx < end; idx += 2) {
        int2 ed = g_edge[idx];
        float w = __int_as_float(ed.y);
        float4 hv = *(const float4*)(hsrc + (size_t)ed.x * OUTD + sub * 4);
        acc.x = fmaf(hv.x, w, acc.x);
        acc.y = fmaf(hv.y, w, acc.y);
        acc.z = fmaf(hv.z, w, acc.z);
        acc.w = fmaf(hv.w, w, acc.w);
    }
    __syncwarp();
    acc.x += __shfl_down_sync(0xffffffffu, acc.x, 16);
    acc.y += __shfl_down_sync(0xffffffffu, acc.y, 16);
    acc.z += __shfl_down_sync(0xffffffffu, acc.z, 16);
    acc.w += __shfl_down_sync(0xffffffffu, acc.w, 16);

    if (half == 0) {
        float4 h0v = *(const float4*)(h0 + (size_t)warp * OUTD + sub * 4);
        float4 outv;
        outv.x = acc.x + ALPHA * h0v.x;
        outv.y = acc.y + ALPHA * h0v.y;
        outv.z = acc.z + ALPHA * h0v.z;
        outv.w = acc.w + ALPHA * h0v.w;
        *(float4*)(hdst + (size_t)warp * OUTD + sub * 4) = outv;
    }
}

// ---------------- host launcher ----------------
extern "C" void kernel_launch(void* const* d_in, const int* in_sizes, int n_in,
                              void* d_out, int out_size)
{
    const float* x    = (const float*)d_in[0];
    const float* W1   = (const float*)d_in[1];
    const float* b1   = (const float*)d_in[2];
    const float* W2   = (const float*)d_in[3];
    const float* b2   = (const float*)d_in[4];
    const float* W3   = (const float*)d_in[5];
    const float* b3   = (const float*)d_in[6];
    const float* ew   = (const float*)d_in[7];
    const int*   erow = (const int*)d_in[8];
    const int*   ecol = (const int*)d_in[9];

    float *h0, *hA, *hB;
    __nv_bfloat16 *h1h, *h1l, *h2h, *h2l;
    __nv_bfloat16 *b1h, *b1l, *b2h, *b2l, *b3h, *b3l;
    cudaGetSymbolAddress((void**)&h1h, g_h1h);
    cudaGetSymbolAddress((void**)&h1l, g_h1l);
    cudaGetSymbolAddress((void**)&h2h, g_h2h);
    cudaGetSymbolAddress((void**)&h2l, g_h2l);
    cudaGetSymbolAddress((void**)&h0, g_h0);
    cudaGetSymbolAddress((void**)&hA, g_hA);
    cudaGetSymbolAddress((void**)&hB, g_hB);
    cudaGetSymbolAddress((void**)&b1h, g_B1h);
    cudaGetSymbolAddress((void**)&b1l, g_B1l);
    cudaGetSymbolAddress((void**)&b2h, g_B2h);
    cudaGetSymbolAddress((void**)&b2l, g_B2l);
    cudaGetSymbolAddress((void**)&b3h, g_B3h);
    cudaGetSymbolAddress((void**)&b3l, g_B3l);

    cudaFuncSetAttribute(gemm_mma_kernel<256, true,  false, true >, cudaFuncAttributeMaxDynamicSharedMemorySize, GEMM_SMEM);
    cudaFuncSetAttribute(gemm_mma_kernel<256, true,  true,  true >, cudaFuncAttributeMaxDynamicSharedMemorySize, GEMM_SMEM);
    cudaFuncSetAttribute(gemm_mma_kernel<64,  false, true,  false>, cudaFuncAttributeMaxDynamicSharedMemorySize, GEMM_SMEM);

    // --- weight transpose + split (first, so a GEMM lands in ncu's capture slot) ---
    splitw_kernel<<<(HID * KPAD1 + 255) / 256, 256>>>(W1, b1h, b1l, IN_DIM, HID, KPAD1);
    splitw_kernel<<<(HID * HID + 255) / 256, 256>>>(W2, b2h, b2l, HID, HID, HID);
    splitw_kernel<<<(OUTD * HID + 255) / 256, 256>>>(W3, b3h, b3l, HID, OUTD, HID);

    // --- MLP on tensor cores (bf16 2-term split, fp32 accumulate) ---
    // GEMM1: fp32 x in, split h1 out.  GEMM2: split in/out.  GEMM3: split in, fp32 h0 out.
    gemm_mma_kernel<256, true,  false, true ><<<dim3(NN / 128, 4), 256, GEMM_SMEM>>>(
        x, nullptr, nullptr, b1h, b1l, b1, nullptr, h1h, h1l, IN_DIM, KPAD1);
    gemm_mma_kernel<256, true,  true,  true ><<<dim3(NN / 128, 4), 256, GEMM_SMEM>>>(
        nullptr, h1h, h1l, b2h, b2l, b2, nullptr, h2h, h2l, HID, HID);
    gemm_mma_kernel<64,  false, true,  false><<<dim3(NN / 128, 1), 256, GEMM_SMEM>>>(
        nullptr, h2h, h2l, b3h, b3l, b3, h0, nullptr, nullptr, HID, HID);

    // --- CSR build (only needed before prop) ---
    zero_cursor_kernel<<<NN / 256, 256>>>();
    hist_kernel<<<EE / 256, 256>>>(erow);
    scan_kernel<<<1, 1024>>>();
    scatter_kernel<<<EE / 256, 256>>>(erow, ecol, ew);

    // --- K=10 propagation steps ---
    float* out = (float*)d_out;
    const float* src = h0;
    for (int s = 0; s < 10; s++) {
        float* dst = (s == 9) ? out : ((s & 1) ? hB : hA);
        prop_kernel<<<(NN * 32) / 256, 256>>>(src, h0, dst);
        src = dst;
    }
}